// round 4
// baseline (speedup 1.0000x reference)
#include <cuda_runtime.h>
#include <cstddef>

// Fixed problem shape: bs=32, V=65536, F=130050, C=6.  BS == warp size.
#define BS 32
#define NV 65536
#define NF 130050
#define NC 6

#define QSCALE 32766.0f
#define QINV   (1.0f / 32766.0f)

// Scratch (device globals):
//   g_ptsT[c][v*32 + b] : fp32 SoA points, 25.2 MB
//   g_fns [c][f*32 + b] : snorm16 SoA face normals, 25.0 MB
__device__ float g_ptsT[3][(size_t)NV * BS];
__device__ short g_fns[3][(size_t)NF * BS];

// ---------------------------------------------------------------------------
// Kernel 1: transpose points (BS,3,V) -> SoA planes [c][v*32+b].
// One 1024-thread block per 32-vertex tile; conflict-free smem; 1 sync.
// ---------------------------------------------------------------------------
__global__ void __launch_bounds__(1024)
transpose_kernel(const float* __restrict__ points)
{
    __shared__ float s[3][32][33];          // [c][v_in_tile][b], pad 33
    int v0   = blockIdx.x * 32;
    int t    = threadIdx.x;
    int b    = t >> 5;                      // 0..31
    int vj   = t & 31;                      // 0..31

    // Coalesced loads: for fixed (b,c) the 32 lanes read 128 contiguous bytes.
#pragma unroll
    for (int c = 0; c < 3; c++)
        s[c][vj][b] = points[((size_t)b * 3 + c) * NV + v0 + vj];
    __syncthreads();

    // Coalesced stores: lane = batch.
    int lane = t & 31;                      // = b (out)
    int j    = t >> 5;                      // = v offset
#pragma unroll
    for (int c = 0; c < 3; c++)
        g_ptsT[c][(size_t)(v0 + j) * BS + lane] = s[c][j][lane];
}

// ---------------------------------------------------------------------------
// Kernel 2: face normals.  warp = face, lane = batch.
// 9 coalesced 128B loads; 3 coalesced 64B snorm16 stores.
// ---------------------------------------------------------------------------
__global__ void __launch_bounds__(256)
face_normals_kernel(const int* __restrict__ faces)
{
    int w    = (blockIdx.x * 256 + threadIdx.x) >> 5;
    int lane = threadIdx.x & 31;            // = batch
    if (w >= NF) return;

    int i0 = __ldg(&faces[3 * w + 0]);
    int i1 = __ldg(&faces[3 * w + 1]);
    int i2 = __ldg(&faces[3 * w + 2]);

    size_t o0 = (size_t)i0 * BS + lane;
    size_t o1 = (size_t)i1 * BS + lane;
    size_t o2 = (size_t)i2 * BS + lane;

    float x0 = g_ptsT[0][o0], y0 = g_ptsT[1][o0], z0 = g_ptsT[2][o0];
    float ax = g_ptsT[0][o1] - x0, ay = g_ptsT[1][o1] - y0, az = g_ptsT[2][o1] - z0;
    float bx = g_ptsT[0][o2] - x0, by = g_ptsT[1][o2] - y0, bz = g_ptsT[2][o2] - z0;

    float cx = ay * bz - az * by;
    float cy = az * bx - ax * bz;
    float cz = ax * by - ay * bx;

    float n   = sqrtf(cx * cx + cy * cy + cz * cz);
    float inv = QSCALE / fmaxf(n, 1e-12f);

    size_t of = (size_t)w * BS + lane;
    g_fns[0][of] = (short)__float2int_rn(cx * inv);
    g_fns[1][of] = (short)__float2int_rn(cy * inv);
    g_fns[2][of] = (short)__float2int_rn(cz * inv);
}

// ---------------------------------------------------------------------------
// Kernel 3: vertex normals.  warp = vertex, lane = batch.
// 18 coalesced 64B snorm16 gathers; decode scale folded into weights.
// ---------------------------------------------------------------------------
__global__ void __launch_bounds__(256)
vertex_normals_kernel(const int*   __restrict__ vti,   // (V, C)
                      const float* __restrict__ vtw,   // (V, C)
                      float*       __restrict__ out)   // (BS, V, 3)
{
    __shared__ float so[8][33][3];          // [v_in_block][b][xyz]

    int wid  = threadIdx.x >> 5;            // 0..7
    int lane = threadIdx.x & 31;            // = batch
    int v0   = blockIdx.x * 8;
    int v    = v0 + wid;

    int   f[NC];
    float wgt[NC];
#pragma unroll
    for (int c = 0; c < NC; c++) {
        f[c]   = __ldg(&vti[v * NC + c]);            // warp-uniform
        wgt[c] = __ldg(&vtw[v * NC + c]) * QINV;     // fold snorm16 decode
    }

    float ax = 0.0f, ay = 0.0f, az = 0.0f;
#pragma unroll
    for (int c = 0; c < NC; c++) {
        size_t o = (size_t)f[c] * BS + lane;
        ax = fmaf((float)g_fns[0][o], wgt[c], ax);
        ay = fmaf((float)g_fns[1][o], wgt[c], ay);
        az = fmaf((float)g_fns[2][o], wgt[c], az);
    }

    float n   = sqrtf(ax * ax + ay * ay + az * az);
    float inv = 1.0f / fmaxf(n, 1e-12f);

    so[wid][lane][0] = ax * inv;
    so[wid][lane][1] = ay * inv;
    so[wid][lane][2] = az * inv;
    __syncthreads();

    // Write out (b, v, 3): thread t -> b = t>>3, j = t&7 writes 12 contiguous B
    int b = threadIdx.x >> 3;
    int j = threadIdx.x & 7;
    size_t o = ((size_t)b * NV + (v0 + j)) * 3;
    out[o + 0] = so[j][b][0];
    out[o + 1] = so[j][b][1];
    out[o + 2] = so[j][b][2];
}

// ---------------------------------------------------------------------------
extern "C" void kernel_launch(void* const* d_in, const int* in_sizes, int n_in,
                              void* d_out, int out_size)
{
    const float* points = (const float*)d_in[0];  // (BS, 3, V)
    const int*   faces  = (const int*)  d_in[1];  // (F, 3)
    const int*   vti    = (const int*)  d_in[2];  // (V, C)
    const float* vtw    = (const float*)d_in[3];  // (V, C, 1)
    float*       out    = (float*)d_out;          // (BS, V, 3)

    transpose_kernel<<<NV / 32, 1024>>>(points);

    {
        int warps_per_block = 8;
        int blocks = (NF + warps_per_block - 1) / warps_per_block;
        face_normals_kernel<<<blocks, 256>>>(faces);
    }

    vertex_normals_kernel<<<NV / 8, 256>>>(vti, vtw, out);
}

// round 5
// speedup vs baseline: 1.0876x; 1.0876x over previous
#include <cuda_runtime.h>
#include <cstddef>

// Fixed problem shape: bs=32, V=65536, F=130050, C=6.  BS == warp size.
#define BS 32
#define NV 65536
#define NF 130050
#define NC 6

#define QSCALE 32766.0f
#define QINV   (1.0f / 32766.0f)

// Scratch (device globals), batch-innermost, coordinate-packed planes:
//   g_ptsXY[v*32+b] = (x,y) float2   : 16.8 MB
//   g_ptsZ [v*32+b] = z float        :  8.4 MB
//   g_fnXY [f*32+b] = (x,y) snorm16  : 16.6 MB
//   g_fnZ  [f*32+b] = z snorm16      :  8.3 MB
__device__ float2 g_ptsXY[(size_t)NV * BS];
__device__ float  g_ptsZ[(size_t)NV * BS];
__device__ short2 g_fnXY[(size_t)NF * BS];
__device__ short  g_fnZ[(size_t)NF * BS];

// ---------------------------------------------------------------------------
// Kernel 1: transpose points (BS,3,V) -> packed planes.
// 64-vertex tile, 256 threads, float4 global loads, single barrier.
// ---------------------------------------------------------------------------
#define TV 64
__global__ void __launch_bounds__(256)
transpose_kernel(const float* __restrict__ points)
{
    __shared__ float s[3][TV][33];          // [c][v_in_tile][b], 25.3 KB
    int v0 = blockIdx.x * TV;
    int t  = threadIdx.x;

    // 96 rows (b*3+c) x 16 float4 = 1536 vector loads; 6 per thread (MLP=6).
#pragma unroll
    for (int k = 0; k < 6; k++) {
        int idx  = t + k * 256;             // 0..1535
        int row  = idx >> 4;                // 0..95 = b*3 + c
        int col4 = idx & 15;
        int b    = row / 3;
        int c    = row - 3 * b;
        float4 p = *(const float4*)&points[(size_t)row * NV + v0 + col4 * 4];
        int vj = col4 * 4;
        s[c][vj + 0][b] = p.x;
        s[c][vj + 1][b] = p.y;
        s[c][vj + 2][b] = p.z;
        s[c][vj + 3][b] = p.w;
    }
    __syncthreads();

    // 8 warps stream 128 warp-rows (64 XY float2-rows, 64 Z float-rows).
    int lane = t & 31;
    int wid  = t >> 5;
#pragma unroll
    for (int r = wid; r < 2 * TV; r += 8) {
        if (r < TV) {
            g_ptsXY[(size_t)(v0 + r) * BS + lane] =
                make_float2(s[0][r][lane], s[1][r][lane]);
        } else {
            int j = r - TV;
            g_ptsZ[(size_t)(v0 + j) * BS + lane] = s[2][j][lane];
        }
    }
}

// ---------------------------------------------------------------------------
// Kernel 2: face normals.  warp = face, lane = batch.
// 3 uniform idx loads + 6 coalesced gathers + 2 coalesced packed stores.
// ---------------------------------------------------------------------------
__global__ void __launch_bounds__(256)
face_normals_kernel(const int* __restrict__ faces)
{
    int w    = (blockIdx.x * 256 + threadIdx.x) >> 5;
    int lane = threadIdx.x & 31;            // = batch
    if (w >= NF) return;

    int i0 = __ldg(&faces[3 * w + 0]);
    int i1 = __ldg(&faces[3 * w + 1]);
    int i2 = __ldg(&faces[3 * w + 2]);

    size_t o0 = (size_t)i0 * BS + lane;
    size_t o1 = (size_t)i1 * BS + lane;
    size_t o2 = (size_t)i2 * BS + lane;

    float2 q0 = g_ptsXY[o0];
    float2 q1 = g_ptsXY[o1];
    float2 q2 = g_ptsXY[o2];
    float  z0 = g_ptsZ[o0];
    float  z1 = g_ptsZ[o1];
    float  z2 = g_ptsZ[o2];

    float ax = q1.x - q0.x, ay = q1.y - q0.y, az = z1 - z0;
    float bx = q2.x - q0.x, by = q2.y - q0.y, bz = z2 - z0;

    float cx = ay * bz - az * by;
    float cy = az * bx - ax * bz;
    float cz = ax * by - ay * bx;

    float n   = sqrtf(cx * cx + cy * cy + cz * cz);
    float inv = QSCALE / fmaxf(n, 1e-12f);

    size_t of = (size_t)w * BS + lane;
    g_fnXY[of] = make_short2((short)__float2int_rn(cx * inv),
                             (short)__float2int_rn(cy * inv));
    g_fnZ[of]  = (short)__float2int_rn(cz * inv);
}

// ---------------------------------------------------------------------------
// Kernel 3: vertex normals.  warp = vertex, lane = batch.
// 6 vectorized uniform loads + 12 coalesced gathers; smem restage for output.
// ---------------------------------------------------------------------------
__global__ void __launch_bounds__(256)
vertex_normals_kernel(const int*   __restrict__ vti,   // (V, C)
                      const float* __restrict__ vtw,   // (V, C)
                      float*       __restrict__ out)   // (BS, V, 3)
{
    __shared__ float so[8][33][3];          // [v_in_block][b][xyz]

    int wid  = threadIdx.x >> 5;            // 0..7
    int lane = threadIdx.x & 31;            // = batch
    int v0   = blockIdx.x * 8;
    int v    = v0 + wid;

    // Rows are 24 B, 8-byte aligned at v*24 -> int2/float2 vector loads.
    const int2*   vti2 = (const int2*)(vti + v * NC);
    const float2* vtw2 = (const float2*)(vtw + v * NC);

    int   f[NC];
    float wgt[NC];
#pragma unroll
    for (int c = 0; c < 3; c++) {
        int2   fi = __ldg(&vti2[c]);
        float2 wi = __ldg(&vtw2[c]);
        f[2 * c + 0]   = fi.x;
        f[2 * c + 1]   = fi.y;
        wgt[2 * c + 0] = wi.x * QINV;       // fold snorm16 decode
        wgt[2 * c + 1] = wi.y * QINV;
    }

    float ax = 0.0f, ay = 0.0f, az = 0.0f;
#pragma unroll
    for (int c = 0; c < NC; c++) {
        size_t o = (size_t)f[c] * BS + lane;
        short2 xy = g_fnXY[o];
        short  zc = g_fnZ[o];
        ax = fmaf((float)xy.x, wgt[c], ax);
        ay = fmaf((float)xy.y, wgt[c], ay);
        az = fmaf((float)zc,   wgt[c], az);
    }

    float n   = sqrtf(ax * ax + ay * ay + az * az);
    float inv = 1.0f / fmaxf(n, 1e-12f);

    so[wid][lane][0] = ax * inv;
    so[wid][lane][1] = ay * inv;
    so[wid][lane][2] = az * inv;
    __syncthreads();

    // Write out (b, v, 3): thread t -> b = t>>3, j = t&7 writes 12 contiguous B
    int b = threadIdx.x >> 3;
    int j = threadIdx.x & 7;
    size_t o = ((size_t)b * NV + (v0 + j)) * 3;
    out[o + 0] = so[j][b][0];
    out[o + 1] = so[j][b][1];
    out[o + 2] = so[j][b][2];
}

// ---------------------------------------------------------------------------
extern "C" void kernel_launch(void* const* d_in, const int* in_sizes, int n_in,
                              void* d_out, int out_size)
{
    const float* points = (const float*)d_in[0];  // (BS, 3, V)
    const int*   faces  = (const int*)  d_in[1];  // (F, 3)
    const int*   vti    = (const int*)  d_in[2];  // (V, C)
    const float* vtw    = (const float*)d_in[3];  // (V, C, 1)
    float*       out    = (float*)d_out;          // (BS, V, 3)

    transpose_kernel<<<NV / TV, 256>>>(points);

    {
        int blocks = (NF + 7) / 8;          // 8 faces per 256-thread block
        face_normals_kernel<<<blocks, 256>>>(faces);
    }

    vertex_normals_kernel<<<NV / 8, 256>>>(vti, vtw, out);
}

// round 6
// speedup vs baseline: 1.0935x; 1.0054x over previous
#include <cuda_runtime.h>
#include <cstddef>

// Fixed problem shape: bs=32, V=65536, F=130050, C=6.  BS == warp size.
#define BS 32
#define NV 65536
#define NF 130050
#define NC 6

#define QSCALE 32766.0f
#define QINV   (1.0f / 32766.0f)

// Scratch (device globals), batch-innermost:
//   g_pts4[v*32+b] = (x,y,z,0) fp32   : 33.6 MB  -> 1 LDG.128 per vertex-gather
//   g_fn4 [f*32+b] = (x,y,z,0) snorm16: 33.3 MB  -> 1 LDG.64  per face-gather
__device__ float4 g_pts4[(size_t)NV * BS];
__device__ short4 g_fn4[(size_t)NF * BS];

// ---------------------------------------------------------------------------
// Kernel 1: transpose points (BS,3,V) -> g_pts4[v*32+b].
// 64-vertex tile, 256 threads, float4 global loads, float4 global stores.
// ---------------------------------------------------------------------------
#define TV 64
__global__ void __launch_bounds__(256)
transpose_kernel(const float* __restrict__ points)
{
    __shared__ float s[3][TV][33];          // [c][v_in_tile][b], 25.3 KB
    int v0 = blockIdx.x * TV;
    int t  = threadIdx.x;

    // Phase 1: 96 rows (b*3+c) x 16 float4 = 1536 vector loads; 6 per thread.
#pragma unroll
    for (int k = 0; k < 6; k++) {
        int idx  = t + k * 256;             // 0..1535
        int row  = idx >> 4;                // 0..95 = b*3 + c
        int col4 = idx & 15;
        int b    = row / 3;
        int c    = row - 3 * b;
        float4 p = *(const float4*)&points[(size_t)row * NV + v0 + col4 * 4];
        int vj = col4 * 4;
        s[c][vj + 0][b] = p.x;
        s[c][vj + 1][b] = p.y;
        s[c][vj + 2][b] = p.z;
        s[c][vj + 3][b] = p.w;
    }
    __syncthreads();

    // Phase 2: 8 warps x 8 rows; 3 conflict-free LDS + 1 STG.128 per iter.
    int lane = t & 31;
    int wid  = t >> 5;
#pragma unroll
    for (int r = wid; r < TV; r += 8) {
        float4 o = make_float4(s[0][r][lane], s[1][r][lane], s[2][r][lane], 0.0f);
        g_pts4[(size_t)(v0 + r) * BS + lane] = o;
    }
}

// ---------------------------------------------------------------------------
// Kernel 2: face normals.  warp = face, lane = batch.
// 3 uniform idx loads + 3 LDG.128 gathers + 1 STG.64 store.
// ---------------------------------------------------------------------------
__global__ void __launch_bounds__(256)
face_normals_kernel(const int* __restrict__ faces)
{
    int w    = (blockIdx.x * 256 + threadIdx.x) >> 5;
    int lane = threadIdx.x & 31;            // = batch
    if (w >= NF) return;

    int i0 = __ldg(&faces[3 * w + 0]);
    int i1 = __ldg(&faces[3 * w + 1]);
    int i2 = __ldg(&faces[3 * w + 2]);

    float4 p0 = g_pts4[(size_t)i0 * BS + lane];
    float4 p1 = g_pts4[(size_t)i1 * BS + lane];
    float4 p2 = g_pts4[(size_t)i2 * BS + lane];

    float ax = p1.x - p0.x, ay = p1.y - p0.y, az = p1.z - p0.z;
    float bx = p2.x - p0.x, by = p2.y - p0.y, bz = p2.z - p0.z;

    float cx = ay * bz - az * by;
    float cy = az * bx - ax * bz;
    float cz = ax * by - ay * bx;

    float ss  = cx * cx + cy * cy + cz * cz;
    float inv = QSCALE * rsqrtf(fmaxf(ss, 1e-24f));

    g_fn4[(size_t)w * BS + lane] =
        make_short4((short)__float2int_rn(cx * inv),
                    (short)__float2int_rn(cy * inv),
                    (short)__float2int_rn(cz * inv), 0);
}

// ---------------------------------------------------------------------------
// Kernel 3: vertex normals.  warp = vertex, lane = batch.
// 6 vectorized uniform loads + 6 LDG.64 gathers; smem restage for output.
// ---------------------------------------------------------------------------
__global__ void __launch_bounds__(256)
vertex_normals_kernel(const int*   __restrict__ vti,   // (V, C)
                      const float* __restrict__ vtw,   // (V, C)
                      float*       __restrict__ out)   // (BS, V, 3)
{
    __shared__ float so[8][33][3];          // [v_in_block][b][xyz]

    int wid  = threadIdx.x >> 5;            // 0..7
    int lane = threadIdx.x & 31;            // = batch
    int v0   = blockIdx.x * 8;
    int v    = v0 + wid;

    // Rows are 24 B, 8-byte aligned at v*24 -> int2/float2 vector loads.
    const int2*   vti2 = (const int2*)(vti + v * NC);
    const float2* vtw2 = (const float2*)(vtw + v * NC);

    int   f[NC];
    float wgt[NC];
#pragma unroll
    for (int c = 0; c < 3; c++) {
        int2   fi = __ldg(&vti2[c]);
        float2 wi = __ldg(&vtw2[c]);
        f[2 * c + 0]   = fi.x;
        f[2 * c + 1]   = fi.y;
        wgt[2 * c + 0] = wi.x * QINV;       // fold snorm16 decode
        wgt[2 * c + 1] = wi.y * QINV;
    }

    float ax = 0.0f, ay = 0.0f, az = 0.0f;
#pragma unroll
    for (int c = 0; c < NC; c++) {
        short4 n = g_fn4[(size_t)f[c] * BS + lane];
        ax = fmaf((float)n.x, wgt[c], ax);
        ay = fmaf((float)n.y, wgt[c], ay);
        az = fmaf((float)n.z, wgt[c], az);
    }

    float ss  = ax * ax + ay * ay + az * az;
    float inv = rsqrtf(fmaxf(ss, 1e-24f));

    so[wid][lane][0] = ax * inv;
    so[wid][lane][1] = ay * inv;
    so[wid][lane][2] = az * inv;
    __syncthreads();

    // Write out (b, v, 3): thread t -> b = t>>3, j = t&7 writes 12 contiguous B
    int b = threadIdx.x >> 3;
    int j = threadIdx.x & 7;
    size_t o = ((size_t)b * NV + (v0 + j)) * 3;
    out[o + 0] = so[j][b][0];
    out[o + 1] = so[j][b][1];
    out[o + 2] = so[j][b][2];
}

// ---------------------------------------------------------------------------
extern "C" void kernel_launch(void* const* d_in, const int* in_sizes, int n_in,
                              void* d_out, int out_size)
{
    const float* points = (const float*)d_in[0];  // (BS, 3, V)
    const int*   faces  = (const int*)  d_in[1];  // (F, 3)
    const int*   vti    = (const int*)  d_in[2];  // (V, C)
    const float* vtw    = (const float*)d_in[3];  // (V, C, 1)
    float*       out    = (float*)d_out;          // (BS, V, 3)

    transpose_kernel<<<NV / TV, 256>>>(points);

    {
        int blocks = (NF + 7) / 8;          // 8 faces per 256-thread block
        face_normals_kernel<<<blocks, 256>>>(faces);
    }

    vertex_normals_kernel<<<NV / 8, 256>>>(vti, vtw, out);
}

// round 7
// speedup vs baseline: 1.1805x; 1.0795x over previous
#include <cuda_runtime.h>
#include <cstddef>

// Fixed problem shape: bs=32, V=65536, F=130050, C=6.  BS == warp size.
#define BS 32
#define NV 65536
#define NF 130050
#define NC 6

#define QSCALE 32766.0f
#define QINV   (1.0f / 32766.0f)

// Scratch (device globals), batch-innermost:
//   g_pts4[v*32+b] = (x,y,z,0) fp32   : 33.6 MB  (1 LDG.128 per vertex-gather)
//   g_fn4 [f*32+b] = (x,y,z,0) snorm16: 33.3 MB  (1 LDG.64  per face-gather)
__device__ float4 g_pts4[(size_t)NV * BS];
__device__ short4 g_fn4[(size_t)NF * BS];

// ---------------------------------------------------------------------------
// Kernel 1: transpose points (BS,3,V) -> g_pts4[v*32+b].
// 64-vertex tile, 256 threads, 8 CTAs/SM forced for latency hiding.
// ---------------------------------------------------------------------------
#define TV 64
__global__ void __launch_bounds__(256, 8)
transpose_kernel(const float* __restrict__ points)
{
    __shared__ float s[3][TV][33];          // [c][v_in_tile][b], 25.3 KB
    int v0 = blockIdx.x * TV;
    int t  = threadIdx.x;

    // Phase 1: 96 rows (b*3+c) x 16 float4 = 1536 vector loads; 6 per thread.
#pragma unroll
    for (int k = 0; k < 6; k++) {
        int idx  = t + k * 256;             // 0..1535
        int row  = idx >> 4;                // 0..95 = b*3 + c
        int col4 = idx & 15;
        int b    = row / 3;
        int c    = row - 3 * b;
        float4 p = __ldg((const float4*)&points[(size_t)row * NV + v0 + col4 * 4]);
        int vj = col4 * 4;
        s[c][vj + 0][b] = p.x;
        s[c][vj + 1][b] = p.y;
        s[c][vj + 2][b] = p.z;
        s[c][vj + 3][b] = p.w;
    }
    __syncthreads();

    // Phase 2: 8 warps x 8 rows; 3 conflict-free LDS + 1 STG.128 per iter.
    int lane = t & 31;
    int wid  = t >> 5;
#pragma unroll
    for (int r = wid; r < TV; r += 8) {
        float4 o = make_float4(s[0][r][lane], s[1][r][lane], s[2][r][lane], 0.0f);
        g_pts4[(size_t)(v0 + r) * BS + lane] = o;
    }
}

// ---------------------------------------------------------------------------
// Kernel 2: face normals.  warp = 2 faces, lane = batch.  MLP = 6 gathers.
// ---------------------------------------------------------------------------
__global__ void __launch_bounds__(256)
face_normals_kernel(const int* __restrict__ faces)
{
    int w    = (blockIdx.x * 256 + threadIdx.x) >> 5;  // warp id
    int lane = threadIdx.x & 31;                       // = batch
    int f0   = 2 * w;
    if (f0 >= NF) return;                              // NF even -> f0+1 valid

    // 6 face-vertex indices for 2 faces: 24B aligned -> 3x int2.
    const int2* fr = (const int2*)(faces + 3 * f0);
    int2 ia = __ldg(&fr[0]);
    int2 ib = __ldg(&fr[1]);
    int2 ic = __ldg(&fr[2]);

    // Issue all 6 gathers up front (independent).
    float4 p0 = g_pts4[(size_t)ia.x * BS + lane];
    float4 p1 = g_pts4[(size_t)ia.y * BS + lane];
    float4 p2 = g_pts4[(size_t)ib.x * BS + lane];
    float4 q0 = g_pts4[(size_t)ib.y * BS + lane];
    float4 q1 = g_pts4[(size_t)ic.x * BS + lane];
    float4 q2 = g_pts4[(size_t)ic.y * BS + lane];

    // Face f0: verts p0,p1,p2
    {
        float ax = p1.x - p0.x, ay = p1.y - p0.y, az = p1.z - p0.z;
        float bx = p2.x - p0.x, by = p2.y - p0.y, bz = p2.z - p0.z;
        float cx = ay * bz - az * by;
        float cy = az * bx - ax * bz;
        float cz = ax * by - ay * bx;
        float inv = QSCALE * rsqrtf(fmaxf(cx*cx + cy*cy + cz*cz, 1e-24f));
        g_fn4[(size_t)f0 * BS + lane] =
            make_short4((short)__float2int_rn(cx * inv),
                        (short)__float2int_rn(cy * inv),
                        (short)__float2int_rn(cz * inv), 0);
    }
    // Face f0+1: verts q0,q1,q2
    {
        float ax = q1.x - q0.x, ay = q1.y - q0.y, az = q1.z - q0.z;
        float bx = q2.x - q0.x, by = q2.y - q0.y, bz = q2.z - q0.z;
        float cx = ay * bz - az * by;
        float cy = az * bx - ax * bz;
        float cz = ax * by - ay * bx;
        float inv = QSCALE * rsqrtf(fmaxf(cx*cx + cy*cy + cz*cz, 1e-24f));
        g_fn4[(size_t)(f0 + 1) * BS + lane] =
            make_short4((short)__float2int_rn(cx * inv),
                        (short)__float2int_rn(cy * inv),
                        (short)__float2int_rn(cz * inv), 0);
    }
}

// ---------------------------------------------------------------------------
// Kernel 3: vertex normals.  warp = 2 vertices, lane = batch.  MLP = 12.
// ---------------------------------------------------------------------------
__global__ void __launch_bounds__(256)
vertex_normals_kernel(const int*   __restrict__ vti,   // (V, C)
                      const float* __restrict__ vtw,   // (V, C)
                      float*       __restrict__ out)   // (BS, V, 3)
{
    __shared__ float so[16][33][3];         // [v_in_block][b][xyz]

    int wid  = threadIdx.x >> 5;            // 0..7
    int lane = threadIdx.x & 31;            // = batch
    int bv0  = blockIdx.x * 16;             // block's first vertex
    int v    = bv0 + wid * 2;               // this warp: v, v+1

    int   f[2 * NC];
    float wgt[2 * NC];
#pragma unroll
    for (int h = 0; h < 2; h++) {
        const int2*   vti2 = (const int2*)(vti + (v + h) * NC);
        const float2* vtw2 = (const float2*)(vtw + (v + h) * NC);
#pragma unroll
        for (int c = 0; c < 3; c++) {
            int2   fi = __ldg(&vti2[c]);
            float2 wi = __ldg(&vtw2[c]);
            f[h * NC + 2 * c + 0]   = fi.x;
            f[h * NC + 2 * c + 1]   = fi.y;
            wgt[h * NC + 2 * c + 0] = wi.x * QINV;
            wgt[h * NC + 2 * c + 1] = wi.y * QINV;
        }
    }

    // 12 independent gathers.
    short4 n[2 * NC];
#pragma unroll
    for (int c = 0; c < 2 * NC; c++)
        n[c] = g_fn4[(size_t)f[c] * BS + lane];

#pragma unroll
    for (int h = 0; h < 2; h++) {
        float ax = 0.0f, ay = 0.0f, az = 0.0f;
#pragma unroll
        for (int c = 0; c < NC; c++) {
            int i = h * NC + c;
            ax = fmaf((float)n[i].x, wgt[i], ax);
            ay = fmaf((float)n[i].y, wgt[i], ay);
            az = fmaf((float)n[i].z, wgt[i], az);
        }
        float inv = rsqrtf(fmaxf(ax*ax + ay*ay + az*az, 1e-24f));
        so[wid * 2 + h][lane][0] = ax * inv;
        so[wid * 2 + h][lane][1] = ay * inv;
        so[wid * 2 + h][lane][2] = az * inv;
    }
    __syncthreads();

    // Write out (b, v, 3): 2 rounds of 8 vertices; 12B contiguous per thread.
    int b = threadIdx.x >> 3;
    int j = threadIdx.x & 7;
#pragma unroll
    for (int h = 0; h < 2; h++) {
        size_t o = ((size_t)b * NV + (bv0 + h * 8 + j)) * 3;
        out[o + 0] = so[h * 8 + j][b][0];
        out[o + 1] = so[h * 8 + j][b][1];
        out[o + 2] = so[h * 8 + j][b][2];
    }
}

// ---------------------------------------------------------------------------
extern "C" void kernel_launch(void* const* d_in, const int* in_sizes, int n_in,
                              void* d_out, int out_size)
{
    const float* points = (const float*)d_in[0];  // (BS, 3, V)
    const int*   faces  = (const int*)  d_in[1];  // (F, 3)
    const int*   vti    = (const int*)  d_in[2];  // (V, C)
    const float* vtw    = (const float*)d_in[3];  // (V, C, 1)
    float*       out    = (float*)d_out;          // (BS, V, 3)

    transpose_kernel<<<NV / TV, 256>>>(points);

    {
        int warps = NF / 2;                 // 65025
        int blocks = (warps + 7) / 8;       // 8 warps per block
        face_normals_kernel<<<blocks, 256>>>(faces);
    }

    vertex_normals_kernel<<<NV / 16, 256>>>(vti, vtw, out);
}